// round 2
// baseline (speedup 1.0000x reference)
#include <cuda_runtime.h>
#include <cuda_fp16.h>

#define ENT_DIM   288
#define REL_R     256
#define RTYPE_DIM 32
#define ROLE_DIM  256
#define N_TRIG    50000
#define N_ARGS    250000
#define ARG_DIM   576
#define OUT_DIM   544

#define BM 128
#define BN 256
#define BK 32
#define NKSTEP 18              // 576 / 32
#define AS_STRIDE 40           // 32 + 8 pad (conflict-free ldmatrix)
#define BS_STRIDE 264          // 256 + 8 pad
#define GTHREADS 512
#define SMEM_BYTES ((2*BM*AS_STRIDE + 2*BK*BS_STRIDE) * 2)   // 54272 B

// -------- device scratch (no allocation allowed) --------
__device__ __half d_Wh[2 * ARG_DIM * ROLE_DIM];   // [g][k][n], g=0 -> W_in
__device__ int    d_perm[2 * N_ARGS];
__device__ int    d_cnt[2];

// -------- tiny prep kernels --------
__global__ void zero_cnt_kernel() {
    if (threadIdx.x < 2) d_cnt[threadIdx.x] = 0;
}

__global__ void partition_kernel(const int* __restrict__ arg_is_in) {
    int i = blockIdx.x * blockDim.x + threadIdx.x;
    if (i >= N_ARGS) return;
    int gi = 1 - arg_is_in[i];            // 0 -> uses W_in, 1 -> uses W_out
    int pos = atomicAdd(&d_cnt[gi], 1);
    d_perm[gi * N_ARGS + pos] = i;
}

__global__ void convw_kernel(const float* __restrict__ W_in,
                             const float* __restrict__ W_out) {
    int i = blockIdx.x * blockDim.x + threadIdx.x;
    if (i >= 2 * ARG_DIM * ROLE_DIM) return;
    float v = (i < ARG_DIM * ROLE_DIM) ? W_in[i] : W_out[i - ARG_DIM * ROLE_DIM];
    d_Wh[i] = __float2half(v);
}

// out[t][0:288] = ent_embeds[trig_ent_id[t]], out[t][288:544] = 0
__global__ void init_out_kernel(const float* __restrict__ ent,
                                const int* __restrict__ trig_ent_id,
                                float* __restrict__ out) {
    int t = blockIdx.x;
    int c = threadIdx.x;                  // 0..135 (float4 units)
    float4 v;
    if (c < ENT_DIM / 4) {
        v = reinterpret_cast<const float4*>(ent)[(size_t)trig_ent_id[t] * (ENT_DIM / 4) + c];
    } else {
        v = make_float4(0.f, 0.f, 0.f, 0.f);
    }
    reinterpret_cast<float4*>(out)[(size_t)t * (OUT_DIM / 4) + c] = v;
}

// -------- main GEMM: y = x @ W_g, x gathered/concatenated on the fly --------
__global__ void __launch_bounds__(GTHREADS, 1)
gemm_kernel(const float* __restrict__ ent,
            const float* __restrict__ rel,
            const float* __restrict__ rtype,
            const int*   __restrict__ rtype_ids,
            const int*   __restrict__ arg_trig,
            const int*   __restrict__ arg_rel,
            const int*   __restrict__ arg_ent,
            float*       __restrict__ out) {
    extern __shared__ __half smem[];
    __half* As = smem;                          // [2][BM][AS_STRIDE]
    __half* Bs = smem + 2 * BM * AS_STRIDE;     // [2][BK][BS_STRIDE]
    __shared__ int s_rel[BM], s_rt[BM], s_ent[BM], s_trig[BM];

    const int g   = blockIdx.z;
    const int m0  = blockIdx.x * BM;
    const int cnt = d_cnt[g];
    if (m0 >= cnt) return;

    const int tid = threadIdx.x;
    if (tid < BM) {
        int r = m0 + tid;
        if (r < cnt) {
            int a  = d_perm[g * N_ARGS + r];
            int rl = arg_rel[a];
            s_rel[tid]  = rl;
            s_rt[tid]   = rtype_ids[rl];
            s_ent[tid]  = arg_ent[a];
            s_trig[tid] = arg_trig[a];
        } else {
            s_rel[tid] = 0; s_rt[tid] = 0; s_ent[tid] = 0; s_trig[tid] = -1;
        }
    }
    __syncthreads();

    const int arow = tid >> 2;            // 128 rows, 4 threads/row
    const int acol = (tid & 3) * 8;       // 8 floats per thread
    const int bk   = tid >> 4;            // 32 k-rows
    const int bn   = (tid & 15) * 16;     // 16 halves per thread
    const __half* Wg = d_Wh + g * (ARG_DIM * ROLE_DIM);

    auto load_a = [&](int ks, float4& v0, float4& v1) {
        const float* src;
        if (ks < 8)       src = rel   + (size_t)s_rel[arow] * REL_R   + ks * 32;
        else if (ks == 8) src = rtype + (size_t)s_rt[arow]  * RTYPE_DIM;
        else              src = ent   + (size_t)s_ent[arow] * ENT_DIM + (ks - 9) * 32;
        v0 = *reinterpret_cast<const float4*>(src + acol);
        v1 = *reinterpret_cast<const float4*>(src + acol + 4);
    };
    auto store_a = [&](int buf, float4 v0, float4 v1) {
        __half2 h0 = __floats2half2_rn(v0.x, v0.y);
        __half2 h1 = __floats2half2_rn(v0.z, v0.w);
        __half2 h2 = __floats2half2_rn(v1.x, v1.y);
        __half2 h3 = __floats2half2_rn(v1.z, v1.w);
        uint4 u;
        u.x = *reinterpret_cast<unsigned*>(&h0);
        u.y = *reinterpret_cast<unsigned*>(&h1);
        u.z = *reinterpret_cast<unsigned*>(&h2);
        u.w = *reinterpret_cast<unsigned*>(&h3);
        *reinterpret_cast<uint4*>(&As[buf * (BM * AS_STRIDE) + arow * AS_STRIDE + acol]) = u;
    };
    auto load_b = [&](int ks, int buf) {
        const __half* src = Wg + (size_t)(ks * BK + bk) * ROLE_DIM + bn;
        unsigned dst = (unsigned)__cvta_generic_to_shared(
            &Bs[buf * (BK * BS_STRIDE) + bk * BS_STRIDE + bn]);
        unsigned long long gsrc = (unsigned long long)__cvta_generic_to_global(src);
        asm volatile("cp.async.cg.shared.global [%0], [%1], 16;" :: "r"(dst), "l"(gsrc) : "memory");
        asm volatile("cp.async.cg.shared.global [%0], [%1], 16;" :: "r"(dst + 16), "l"(gsrc + 16) : "memory");
    };

    const int lane = tid & 31;
    const int wid  = tid >> 5;
    const int wm   = (wid & 3) * 32;      // warp M base (4 warps over M)
    const int wn   = (wid >> 2) * 64;     // warp N base (4 warps over N)

    float acc[2][8][4];
    #pragma unroll
    for (int i = 0; i < 2; i++)
        #pragma unroll
        for (int j = 0; j < 8; j++)
            #pragma unroll
            for (int q = 0; q < 4; q++) acc[i][j][q] = 0.f;

    float4 av0, av1;
    load_a(0, av0, av1);
    load_b(0, 0);
    asm volatile("cp.async.commit_group;" ::: "memory");
    store_a(0, av0, av1);
    asm volatile("cp.async.wait_group 0;" ::: "memory");
    __syncthreads();

    for (int ks = 0; ks < NKSTEP; ks++) {
        const int p = ks & 1;
        const bool more = (ks + 1 < NKSTEP);
        if (more) {
            load_a(ks + 1, av0, av1);
            load_b(ks + 1, p ^ 1);
            asm volatile("cp.async.commit_group;" ::: "memory");
        }
        const __half* Ab = As + p * (BM * AS_STRIDE);
        const __half* Bb = Bs + p * (BK * BS_STRIDE);
        #pragma unroll
        for (int kk = 0; kk < 2; kk++) {
            unsigned a[2][4];
            #pragma unroll
            for (int mi = 0; mi < 2; mi++) {
                unsigned addr = (unsigned)__cvta_generic_to_shared(
                    Ab + (wm + mi * 16 + (lane & 15)) * AS_STRIDE + kk * 16 + (lane >> 4) * 8);
                asm volatile("ldmatrix.sync.aligned.m8n8.x4.shared.b16 {%0,%1,%2,%3}, [%4];"
                             : "=r"(a[mi][0]), "=r"(a[mi][1]), "=r"(a[mi][2]), "=r"(a[mi][3])
                             : "r"(addr));
            }
            #pragma unroll
            for (int nj = 0; nj < 4; nj++) {
                unsigned b[4];
                unsigned baddr = (unsigned)__cvta_generic_to_shared(
                    Bb + (kk * 16 + (lane & 15)) * BS_STRIDE + wn + nj * 16 + (lane >> 4) * 8);
                asm volatile("ldmatrix.sync.aligned.m8n8.x4.trans.shared.b16 {%0,%1,%2,%3}, [%4];"
                             : "=r"(b[0]), "=r"(b[1]), "=r"(b[2]), "=r"(b[3])
                             : "r"(baddr));
                #pragma unroll
                for (int mi = 0; mi < 2; mi++) {
                    asm volatile("mma.sync.aligned.m16n8k16.row.col.f32.f16.f16.f32 "
                                 "{%0,%1,%2,%3}, {%4,%5,%6,%7}, {%8,%9}, {%0,%1,%2,%3};"
                                 : "+f"(acc[mi][2 * nj][0]), "+f"(acc[mi][2 * nj][1]),
                                   "+f"(acc[mi][2 * nj][2]), "+f"(acc[mi][2 * nj][3])
                                 : "r"(a[mi][0]), "r"(a[mi][1]), "r"(a[mi][2]), "r"(a[mi][3]),
                                   "r"(b[0]), "r"(b[1]));
                    asm volatile("mma.sync.aligned.m16n8k16.row.col.f32.f16.f16.f32 "
                                 "{%0,%1,%2,%3}, {%4,%5,%6,%7}, {%8,%9}, {%0,%1,%2,%3};"
                                 : "+f"(acc[mi][2 * nj + 1][0]), "+f"(acc[mi][2 * nj + 1][1]),
                                   "+f"(acc[mi][2 * nj + 1][2]), "+f"(acc[mi][2 * nj + 1][3])
                                 : "r"(a[mi][0]), "r"(a[mi][1]), "r"(a[mi][2]), "r"(a[mi][3]),
                                   "r"(b[2]), "r"(b[3]));
                }
            }
        }
        if (more) store_a(p ^ 1, av0, av1);
        asm volatile("cp.async.wait_group 0;" ::: "memory");
        __syncthreads();
    }

    // epilogue: segment-sum via vector reductions keyed by per-row trigger
    #pragma unroll
    for (int mi = 0; mi < 2; mi++) {
        int rl = wm + mi * 16 + (lane >> 2);
        int t0 = s_trig[rl];
        int t1 = s_trig[rl + 8];
        #pragma unroll
        for (int f = 0; f < 8; f++) {
            int c = ENT_DIM + wn + f * 8 + (lane & 3) * 2;
            if (t0 >= 0) {
                float* p0 = out + (size_t)t0 * OUT_DIM + c;
                asm volatile("red.global.add.v2.f32 [%0], {%1,%2};"
                             :: "l"(p0), "f"(acc[mi][f][0]), "f"(acc[mi][f][1]) : "memory");
            }
            if (t1 >= 0) {
                float* p1 = out + (size_t)t1 * OUT_DIM + c;
                asm volatile("red.global.add.v2.f32 [%0], {%1,%2};"
                             :: "l"(p1), "f"(acc[mi][f][2]), "f"(acc[mi][f][3]) : "memory");
            }
        }
    }
}

extern "C" void kernel_launch(void* const* d_in, const int* in_sizes, int n_in,
                              void* d_out, int out_size) {
    const float* ent        = (const float*)d_in[0];
    const float* rel        = (const float*)d_in[1];
    const float* rtype      = (const float*)d_in[2];
    const float* W_in       = (const float*)d_in[3];
    const float* W_out      = (const float*)d_in[4];
    const int* rtype_ids    = (const int*)d_in[5];
    const int* trig_ent_id  = (const int*)d_in[6];
    const int* arg_trig     = (const int*)d_in[7];
    const int* arg_rel      = (const int*)d_in[8];
    const int* arg_ent      = (const int*)d_in[9];
    const int* arg_is_in    = (const int*)d_in[10];
    float* out = (float*)d_out;

    cudaFuncSetAttribute(gemm_kernel, cudaFuncAttributeMaxDynamicSharedMemorySize, SMEM_BYTES);

    zero_cnt_kernel<<<1, 32>>>();
    partition_kernel<<<(N_ARGS + 255) / 256, 256>>>(arg_is_in);
    convw_kernel<<<(2 * ARG_DIM * ROLE_DIM + 255) / 256, 256>>>(W_in, W_out);
    init_out_kernel<<<N_TRIG, OUT_DIM / 4>>>(ent, trig_ent_id, out);

    dim3 grid((N_ARGS + BM - 1) / BM, 1, 2);
    gemm_kernel<<<grid, GTHREADS, SMEM_BYTES>>>(ent, rel, rtype, rtype_ids,
                                                arg_trig, arg_rel, arg_ent, out);
}